// round 15
// baseline (speedup 1.0000x reference)
#include <cuda_runtime.h>
#include <cuda_fp16.h>
#include <cstdint>
#include <cstddef>

#define NB   16
#define FIN  512
#define TD   512
#define MR   8192
#define HD   2048

#define BM   128
#define BN   128
#define LDROW 144
#define TILEB (128 * LDROW)              // 18432 B
#define STAGEB (2 * TILEB)               // 36864 B
#define SMEM_L1 (3 * STAGEB)             // 110592 B (gemm_l1: 3 stages, 2 CTAs)
#define SMEM_F16 (2 * STAGEB)            // 73728 B  (gemm_f16: 2 stages, 3 CTAs)
#define SMEM_CMB (128 * 132 * 4)         // 67584 B  (combine transpose)

// ---------------- scratch ----------------------------------------------------
__device__ __half g_xt2[(size_t)MR * 1024];
__device__ __half g_w1b[(size_t)HD * 1024];
__device__ __half g_wb[(size_t)2 * HD * HD + (size_t)FIN * HD];
__device__ float  g_h[(size_t)MR * HD];   // layer1 f32; layers2/3 f16; L4 partials
__device__ __half g_a[(size_t)MR * HD];
__device__ float g_mu[HD], g_rs[HD];
__device__ float g_ps2[128 * HD], g_pq2[128 * HD];

__device__ __forceinline__ float sgnf(float v) {
    return (v > 0.f) ? 1.f : ((v < 0.f) ? -1.f : 0.f);
}
__device__ __forceinline__ uint32_t smem_u32(const void* p) {
    return (uint32_t)__cvta_generic_to_shared(p);
}
__device__ __forceinline__ void cp16(uint32_t dst, const void* src) {
    asm volatile("cp.async.cg.shared.global [%0], [%1], 16;" :: "r"(dst), "l"(src));
}
__device__ __forceinline__ void ldsm4(uint32_t& r0, uint32_t& r1, uint32_t& r2, uint32_t& r3,
                                      uint32_t a) {
    asm volatile("ldmatrix.sync.aligned.m8n8.x4.shared.b16 {%0,%1,%2,%3}, [%4];"
                 : "=r"(r0), "=r"(r1), "=r"(r2), "=r"(r3) : "r"(a));
}
__device__ __forceinline__ void mma_f16_f32(float* c, const uint32_t* a, const uint32_t* b) {
    asm volatile("mma.sync.aligned.m16n8k16.row.col.f32.f16.f16.f32 "
                 "{%0,%1,%2,%3},{%4,%5,%6,%7},{%8,%9},{%0,%1,%2,%3};"
                 : "+f"(c[0]), "+f"(c[1]), "+f"(c[2]), "+f"(c[3])
                 : "r"(a[0]), "r"(a[1]), "r"(a[2]), "r"(a[3]), "r"(b[0]), "r"(b[1]));
}
__device__ __forceinline__ void mma_f16_f16(uint32_t* c, const uint32_t* a, const uint32_t* b) {
    asm volatile("mma.sync.aligned.m16n8k16.row.col.f16.f16.f16.f16 "
                 "{%0,%1},{%2,%3,%4,%5},{%6,%7},{%0,%1};"
                 : "+r"(c[0]), "+r"(c[1])
                 : "r"(a[0]), "r"(a[1]), "r"(a[2]), "r"(a[3]), "r"(b[0]), "r"(b[1]));
}

// ---------------- tile loader: 128 rows x 128B of K per stage -------------------
__device__ __forceinline__ void load_stage(
    const char* __restrict__ A, const char* __restrict__ B,
    size_t Kb, int bm, int bn, uint32_t smbase, int tid, int stage, int kc)
{
    uint32_t sA = smbase + stage * STAGEB;
    uint32_t sB = sA + TILEB;
    const char* gA = A + (size_t)bm * Kb + (size_t)kc * 128;
    const char* gB = B + (size_t)bn * Kb + (size_t)kc * 128;
#pragma unroll
    for (int i = 0; i < 4; i++) {
        int idx = tid + i * 256;
        int r = idx >> 3, c = idx & 7;
        cp16(sA + r * LDROW + c * 16, gA + (size_t)r * Kb + c * 16);
    }
#pragma unroll
    for (int i = 0; i < 4; i++) {
        int idx = tid + i * 256;
        int r = idx >> 3, c = idx & 7;
        cp16(sB + r * LDROW + c * 16, gB + (size_t)r * Kb + c * 16);
    }
    asm volatile("cp.async.commit_group;" ::: "memory");
}

// ---------------- f16-in / f32-acc GEMM (layer 1) + fused stats + weight binarize
__global__ void __launch_bounds__(256, 2)
gemm_l1(const __half* __restrict__ A, const __half* __restrict__ B,
        float* __restrict__ C, int N, int K,
        float* __restrict__ ps2, float* __restrict__ pq2,
        const float* __restrict__ W2, const float* __restrict__ W3,
        const float* __restrict__ W4, __half* __restrict__ wb)
{
    extern __shared__ char smraw[];
    const uint32_t smbase = smem_u32(smraw);
    const int tid = threadIdx.x, wid = tid >> 5, lid = tid & 31;
    const int bm = blockIdx.y * BM, bn = blockIdx.x * BN;
    const int NC = K / 64;
    const int wm = (wid & 1) * 64, wn = (wid >> 1) * 32;
    const int lr = ((lid >> 3) & 1) * 8 + (lid & 7);
    const int lc = (lid >> 4) * 8;
    const size_t Kb = (size_t)K * 2;

    float acc[4][4][4];
#pragma unroll
    for (int i = 0; i < 4; i++)
#pragma unroll
        for (int j = 0; j < 4; j++)
#pragma unroll
            for (int q = 0; q < 4; q++) acc[i][j][q] = 0.f;

    load_stage((const char*)A, (const char*)B, Kb, bm, bn, smbase, tid, 0, 0);
    load_stage((const char*)A, (const char*)B, Kb, bm, bn, smbase, tid, 1, 1);

    int st = 0;
    for (int kc = 0; kc < NC; ++kc) {
        asm volatile("cp.async.wait_group 1;" ::: "memory");
        __syncthreads();
        const uint32_t aBase = smbase + st * STAGEB;
        const uint32_t bBase = aBase + TILEB;
#pragma unroll
        for (int ks = 0; ks < 4; ++ks) {
            uint32_t a[4][4];
#pragma unroll
            for (int i = 0; i < 4; i++)
                ldsm4(a[i][0], a[i][1], a[i][2], a[i][3],
                      aBase + (uint32_t)(wm + i * 16 + lr) * LDROW
                            + (uint32_t)(ks * 16 + lc) * 2);
            uint32_t b[4][2];
#pragma unroll
            for (int jj = 0; jj < 2; jj++) {
                uint32_t r0, r1, r2, r3;
                ldsm4(r0, r1, r2, r3,
                      bBase + (uint32_t)(wn + jj * 16 + lr) * LDROW
                            + (uint32_t)(ks * 16 + lc) * 2);
                b[jj * 2 + 0][0] = r0; b[jj * 2 + 0][1] = r2;
                b[jj * 2 + 1][0] = r1; b[jj * 2 + 1][1] = r3;
            }
#pragma unroll
            for (int i = 0; i < 4; i++)
#pragma unroll
                for (int j = 0; j < 4; j++)
                    mma_f16_f32(acc[i][j], a[i], b[j]);
        }
        int nk = kc + 2;
        if (nk < NC) {
            int nst = st + 2; if (nst >= 3) nst -= 3;
            load_stage((const char*)A, (const char*)B, Kb, bm, bn, smbase, tid, nst, nk);
        } else
            asm volatile("cp.async.commit_group;" ::: "memory");
        if (++st == 3) st = 0;
    }

    const int row0 = lid >> 2, col0 = (lid & 3) * 2;
#pragma unroll
    for (int i = 0; i < 4; i++)
#pragma unroll
        for (int j = 0; j < 4; j++) {
            int m0 = bm + wm + i * 16 + row0;
            int n0 = bn + wn + j * 8 + col0;
            *(float2*)&C[(size_t)m0 * N + n0]       = make_float2(acc[i][j][0], acc[i][j][1]);
            *(float2*)&C[(size_t)(m0 + 8) * N + n0] = make_float2(acc[i][j][2], acc[i][j][3]);
        }
    // fused per-warp column stats
#pragma unroll
    for (int j = 0; j < 4; j++) {
        float s0 = 0.f, s1 = 0.f, q0 = 0.f, q1 = 0.f;
#pragma unroll
        for (int i = 0; i < 4; i++) {
            float a0 = acc[i][j][0], a1 = acc[i][j][2];
            float b0 = acc[i][j][1], b1 = acc[i][j][3];
            s0 += a0 + a1;  q0 += a0 * a0 + a1 * a1;
            s1 += b0 + b1;  q1 += b0 * b0 + b1 * b1;
        }
#pragma unroll
        for (int d = 4; d < 32; d <<= 1) {
            s0 += __shfl_xor_sync(0xFFFFFFFFu, s0, d);
            s1 += __shfl_xor_sync(0xFFFFFFFFu, s1, d);
            q0 += __shfl_xor_sync(0xFFFFFFFFu, q0, d);
            q1 += __shfl_xor_sync(0xFFFFFFFFu, q1, d);
        }
        if (lid < 4) {
            int prow = (int)blockIdx.y * 2 + (wid & 1);
            int col  = bn + wn + j * 8 + (lid & 3) * 2;
            *(float2*)&ps2[(size_t)prow * HD + col] = make_float2(s0, s1);
            *(float2*)&pq2[(size_t)prow * HD + col] = make_float2(q0, q1);
        }
    }
    // folded weight binarization (W2|W3|W4 -> wb), grid-stride over 8-elem chunks
    {
        const int C2 = HD * HD / 8, C3 = 2 * C2, C4 = C3 + FIN * HD / 8;
        int base = (int)(blockIdx.y * gridDim.x + blockIdx.x) * 256 + tid;
        int stride = (int)(gridDim.x * gridDim.y) * 256;
        for (int i = base; i < C4; i += stride) {
            const float* src;
            size_t off;
            if (i < C2)      { src = W2; off = (size_t)i * 8; }
            else if (i < C3) { src = W3; off = (size_t)(i - C2) * 8; }
            else             { src = W4; off = (size_t)(i - C3) * 8; }
            float4 w0 = *(const float4*)&src[off];
            float4 w1 = *(const float4*)&src[off + 4];
            __half2 p0 = __floats2half2_rn(sgnf(w0.x), sgnf(w0.y));
            __half2 p1 = __floats2half2_rn(sgnf(w0.z), sgnf(w0.w));
            __half2 p2 = __floats2half2_rn(sgnf(w1.x), sgnf(w1.y));
            __half2 p3 = __floats2half2_rn(sgnf(w1.z), sgnf(w1.w));
            uint4 v;
            v.x = *(uint32_t*)&p0; v.y = *(uint32_t*)&p1;
            v.z = *(uint32_t*)&p2; v.w = *(uint32_t*)&p3;
            *(uint4*)&wb[(size_t)i * 8] = v;
        }
    }
}

// ---------------- f16/f16 GEMM: EPI 0 = h+stats, EPI 1 = scale+transpose,
//                  EPI 2 = split-K partial (blockIdx.z = K half) ----------------
template <int EPI>
__global__ void __launch_bounds__(256, 3)
gemm_f16(const __half* __restrict__ A, const __half* __restrict__ B,
         void* __restrict__ Cv, int N, int K, const float* __restrict__ scale,
         float* __restrict__ ps2, float* __restrict__ pq2)
{
    extern __shared__ char smraw[];
    const uint32_t smbase = smem_u32(smraw);
    const int tid = threadIdx.x, wid = tid >> 5, lid = tid & 31;
    const int bm = blockIdx.y * BM, bn = blockIdx.x * BN;
    const int NC = (EPI == 2) ? (K / 128) : (K / 64);
    const int kcb = (EPI == 2) ? (int)blockIdx.z * NC : 0;
    const int wm = (wid & 1) * 64, wn = (wid >> 1) * 32;
    const int lr = ((lid >> 3) & 1) * 8 + (lid & 7);
    const int lc = (lid >> 4) * 8;
    const size_t Kb = (size_t)K * 2;

    uint32_t acc[4][4][2];
#pragma unroll
    for (int i = 0; i < 4; i++)
#pragma unroll
        for (int j = 0; j < 4; j++) { acc[i][j][0] = 0u; acc[i][j][1] = 0u; }

    load_stage((const char*)A, (const char*)B, Kb, bm, bn, smbase, tid, 0, kcb);

    int st = 0;
    for (int kc = 0; kc < NC; ++kc) {
        asm volatile("cp.async.wait_group 0;" ::: "memory");
        __syncthreads();
        if (kc + 1 < NC)
            load_stage((const char*)A, (const char*)B, Kb, bm, bn, smbase, tid,
                       st ^ 1, kcb + kc + 1);
        const uint32_t aBase = smbase + st * STAGEB;
        const uint32_t bBase = aBase + TILEB;
#pragma unroll
        for (int ks = 0; ks < 4; ++ks) {
            uint32_t a[4][4];
#pragma unroll
            for (int i = 0; i < 4; i++)
                ldsm4(a[i][0], a[i][1], a[i][2], a[i][3],
                      aBase + (uint32_t)(wm + i * 16 + lr) * LDROW
                            + (uint32_t)(ks * 16 + lc) * 2);
            uint32_t b[4][2];
#pragma unroll
            for (int jj = 0; jj < 2; jj++) {
                uint32_t r0, r1, r2, r3;
                ldsm4(r0, r1, r2, r3,
                      bBase + (uint32_t)(wn + jj * 16 + lr) * LDROW
                            + (uint32_t)(ks * 16 + lc) * 2);
                b[jj * 2 + 0][0] = r0; b[jj * 2 + 0][1] = r2;
                b[jj * 2 + 1][0] = r1; b[jj * 2 + 1][1] = r3;
            }
#pragma unroll
            for (int i = 0; i < 4; i++)
#pragma unroll
                for (int j = 0; j < 4; j++)
                    mma_f16_f16(acc[i][j], a[i], b[j]);
        }
        st ^= 1;
    }

    const int row0 = lid >> 2, col0 = (lid & 3) * 2;
    if (EPI == 0 || EPI == 2) {
        __half* C = (__half*)Cv;
        if (EPI == 2) C += (size_t)blockIdx.z * MR * FIN;
#pragma unroll
        for (int i = 0; i < 4; i++)
#pragma unroll
            for (int j = 0; j < 4; j++) {
                int m0 = bm + wm + i * 16 + row0;
                int n0 = bn + wn + j * 8 + col0;
                *(uint32_t*)&C[(size_t)m0 * N + n0]       = acc[i][j][0];
                *(uint32_t*)&C[(size_t)(m0 + 8) * N + n0] = acc[i][j][1];
            }
        if (EPI == 0) {
#pragma unroll
            for (int j = 0; j < 4; j++) {
                float s0 = 0.f, s1 = 0.f, q0 = 0.f, q1 = 0.f;
#pragma unroll
                for (int i = 0; i < 4; i++) {
                    __half2 v0 = *(__half2*)&acc[i][j][0];
                    __half2 v1 = *(__half2*)&acc[i][j][1];
                    float a0 = __low2float(v0), b0 = __high2float(v0);
                    float a1 = __low2float(v1), b1 = __high2float(v1);
                    s0 += a0 + a1;  q0 += a0 * a0 + a1 * a1;
                    s1 += b0 + b1;  q1 += b0 * b0 + b1 * b1;
                }
#pragma unroll
                for (int d = 4; d < 32; d <<= 1) {
                    s0 += __shfl_xor_sync(0xFFFFFFFFu, s0, d);
                    s1 += __shfl_xor_sync(0xFFFFFFFFu, s1, d);
                    q0 += __shfl_xor_sync(0xFFFFFFFFu, q0, d);
                    q1 += __shfl_xor_sync(0xFFFFFFFFu, q1, d);
                }
                if (lid < 4) {
                    int prow = (int)blockIdx.y * 2 + (wid & 1);
                    int col  = bn + wn + j * 8 + (lid & 3) * 2;
                    *(float2*)&ps2[(size_t)prow * HD + col] = make_float2(s0, s1);
                    *(float2*)&pq2[(size_t)prow * HD + col] = make_float2(q0, q1);
                }
            }
        }
    } else {
        float* trans = (float*)smraw;
        __syncthreads();
#pragma unroll
        for (int j = 0; j < 4; j++) {
            int n0 = wn + j * 8 + col0;
            float s0 = scale[bn + n0], s1 = scale[bn + n0 + 1];
#pragma unroll
            for (int i = 0; i < 4; i++) {
                int t0 = wm + i * 16 + row0;
                __half2 v0 = *(__half2*)&acc[i][j][0];
                __half2 v1 = *(__half2*)&acc[i][j][1];
                trans[n0 * 132 + t0]           = __low2float(v0) * s0;
                trans[(n0 + 1) * 132 + t0]     = __high2float(v0) * s1;
                trans[n0 * 132 + t0 + 8]       = __low2float(v1) * s0;
                trans[(n0 + 1) * 132 + t0 + 8] = __high2float(v1) * s1;
            }
        }
        __syncthreads();
        float* y = (float*)Cv;
        const int b0 = bm >> 9;
        const int tb = bm & 511;
        const int n = tid >> 1, half = tid & 1;
        float* yp = y + ((size_t)b0 * FIN + bn + n) * TD + tb + half * 64;
        const float* sp = trans + n * 132 + half * 64;
#pragma unroll
        for (int k = 0; k < 16; k++)
            *(float4*)&yp[k * 4] = *(const float4*)&sp[k * 4];
    }
}

// ---------------- L4 split-K combine: y = (p0+p1)*scale, transposed store -------
__global__ void __launch_bounds__(256, 3)
combine_l4(const __half* __restrict__ part, float* __restrict__ y,
           const float* __restrict__ scale)
{
    extern __shared__ float trans[];          // 128 x 132
    const int bn = blockIdx.x * 128, bm = blockIdx.y * 128;
    const int tid = threadIdx.x;
    const __half* p0 = part + (size_t)bm * FIN + bn;
    const __half* p1 = p0 + (size_t)MR * FIN;
#pragma unroll
    for (int it = 0; it < 8; ++it) {
        int e = (tid + it * 256) * 8;          // elem index within 128x128 tile
        int r = e >> 7, c = e & 127;
        uint4 v0 = *(const uint4*)&p0[(size_t)r * FIN + c];
        uint4 v1 = *(const uint4*)&p1[(size_t)r * FIN + c];
        const __half2* a0 = (const __half2*)&v0;
        const __half2* a1 = (const __half2*)&v1;
#pragma unroll
        for (int q = 0; q < 4; q++) {
            int cc = c + q * 2;
            float lo = __low2float(a0[q])  + __low2float(a1[q]);
            float hi = __high2float(a0[q]) + __high2float(a1[q]);
            trans[cc * 132 + r]       = lo * scale[bn + cc];
            trans[(cc + 1) * 132 + r] = hi * scale[bn + cc + 1];
        }
    }
    __syncthreads();
    const int b0 = bm >> 9, tb = bm & 511;
    const int n = tid >> 1, half = tid & 1;
    float* yp = y + ((size_t)b0 * FIN + bn + n) * TD + tb + half * 64;
    const float* sp = trans + n * 132 + half * 64;
#pragma unroll
    for (int k = 0; k < 16; k++)
        *(float4*)&yp[k * 4] = *(const float4*)&sp[k * 4];
}

// ---------------- prep kernels -------------------------------------------------
__global__ void transpose_split2(const float* __restrict__ x, __half* __restrict__ xt2) {
    __shared__ float tile[32][33];
    int n = blockIdx.z, t0 = blockIdx.x * 32, f0 = blockIdx.y * 32;
    const float* xp = x + (size_t)n * FIN * TD;
#pragma unroll
    for (int i = 0; i < 4; i++) {
        int f = f0 + threadIdx.y + i * 8;
        tile[threadIdx.y + i * 8][threadIdx.x] = xp[(size_t)f * TD + t0 + threadIdx.x];
    }
    __syncthreads();
#pragma unroll
    for (int i = 0; i < 4; i++) {
        int t = t0 + threadIdx.y + i * 8;
        int f = f0 + threadIdx.x;
        float v = tile[threadIdx.x][threadIdx.y + i * 8];
        __half hi = __float2half_rn(v);
        float r1 = v - __half2float(hi);
        __half lo = __float2half_rn(r1);
        size_t row = (size_t)((size_t)n * TD + t) * 1024;
        xt2[row + f] = hi;
        xt2[row + 512 + f] = lo;
    }
}

__global__ void binw1(const float* __restrict__ W1, __half* __restrict__ o) {
    int i = blockIdx.x * 256 + threadIdx.x;
    if (i >= HD * FIN / 8) return;
    float4 w0 = *(const float4*)&W1[(size_t)i * 8];
    float4 w1 = *(const float4*)&W1[(size_t)i * 8 + 4];
    int row = (i * 8) >> 9, k = (i * 8) & 511;
    __half2 p0 = __floats2half2_rn(sgnf(w0.x), sgnf(w0.y));
    __half2 p1 = __floats2half2_rn(sgnf(w0.z), sgnf(w0.w));
    __half2 p2 = __floats2half2_rn(sgnf(w1.x), sgnf(w1.y));
    __half2 p3 = __floats2half2_rn(sgnf(w1.z), sgnf(w1.w));
    uint4 v;
    v.x = *(uint32_t*)&p0; v.y = *(uint32_t*)&p1;
    v.z = *(uint32_t*)&p2; v.w = *(uint32_t*)&p3;
    size_t base = (size_t)row * 1024 + k;
    *(uint4*)&o[base] = v;
    *(uint4*)&o[base + 512] = v;
}

// ---------------- BN stats: 128-partial reduce ----------------------------------
__global__ void stats_final128(const float* __restrict__ ps2, const float* __restrict__ pq2,
                               float* __restrict__ mu, float* __restrict__ rs) {
    int col = blockIdx.x * 256 + threadIdx.x;
    if (col >= HD) return;
    float s = 0.f, sq = 0.f;
    for (int p = 0; p < 128; p++) { s += ps2[(size_t)p * HD + col]; sq += pq2[(size_t)p * HD + col]; }
    float m = s * (1.f / MR);
    float var = sq * (1.f / MR) - m * m;
    if (var < 0.f) var = 0.f;
    mu[col] = m;
    rs[col] = rsqrtf(var + 1e-5f);
}

// ---------------- sign activations (8 elems/thread) ------------------------------
__global__ void sign_act_f32(const float* __restrict__ h,
                             const float* __restrict__ mu, const float* __restrict__ rs,
                             const float* __restrict__ g, const float* __restrict__ b,
                             __half* __restrict__ a) {
    size_t i8 = (size_t)blockIdx.x * blockDim.x + threadIdx.x;
    size_t e0 = i8 * 8;
    if (e0 >= (size_t)MR * HD) return;
    int j = (int)(e0 % HD);
    float4 h0 = *(const float4*)&h[e0];
    float4 h1 = *(const float4*)&h[e0 + 4];
    float4 m0 = *(const float4*)&mu[j], m1 = *(const float4*)&mu[j + 4];
    float4 r0 = *(const float4*)&rs[j], r1 = *(const float4*)&rs[j + 4];
    float4 g0 = *(const float4*)&g[j],  g1 = *(const float4*)&g[j + 4];
    float4 b0 = *(const float4*)&b[j],  b1 = *(const float4*)&b[j + 4];
    __half2 p0 = __floats2half2_rn(sgnf(g0.x * (h0.x - m0.x) * r0.x + b0.x),
                                   sgnf(g0.y * (h0.y - m0.y) * r0.y + b0.y));
    __half2 p1 = __floats2half2_rn(sgnf(g0.z * (h0.z - m0.z) * r0.z + b0.z),
                                   sgnf(g0.w * (h0.w - m0.w) * r0.w + b0.w));
    __half2 p2 = __floats2half2_rn(sgnf(g1.x * (h1.x - m1.x) * r1.x + b1.x),
                                   sgnf(g1.y * (h1.y - m1.y) * r1.y + b1.y));
    __half2 p3 = __floats2half2_rn(sgnf(g1.z * (h1.z - m1.z) * r1.z + b1.z),
                                   sgnf(g1.w * (h1.w - m1.w) * r1.w + b1.w));
    uint4 v;
    v.x = *(uint32_t*)&p0; v.y = *(uint32_t*)&p1;
    v.z = *(uint32_t*)&p2; v.w = *(uint32_t*)&p3;
    *(uint4*)&a[e0] = v;
}
__global__ void sign_act_f16(const __half* __restrict__ h,
                             const float* __restrict__ mu, const float* __restrict__ rs,
                             const float* __restrict__ g, const float* __restrict__ b,
                             __half* __restrict__ a) {
    size_t i8 = (size_t)blockIdx.x * blockDim.x + threadIdx.x;
    size_t e0 = i8 * 8;
    if (e0 >= (size_t)MR * HD) return;
    int j = (int)(e0 % HD);
    uint4 hv = *(const uint4*)&h[e0];
    const __half2* hp = (const __half2*)&hv;
    float4 m0 = *(const float4*)&mu[j], m1 = *(const float4*)&mu[j + 4];
    float4 r0 = *(const float4*)&rs[j], r1 = *(const float4*)&rs[j + 4];
    float4 g0 = *(const float4*)&g[j],  g1 = *(const float4*)&g[j + 4];
    float4 b0 = *(const float4*)&b[j],  b1 = *(const float4*)&b[j + 4];
    __half2 p0 = __floats2half2_rn(
        sgnf(g0.x * (__low2float(hp[0]) - m0.x) * r0.x + b0.x),
        sgnf(g0.y * (__high2float(hp[0]) - m0.y) * r0.y + b0.y));
    __half2 p1 = __floats2half2_rn(
        sgnf(g0.z * (__low2float(hp[1]) - m0.z) * r0.z + b0.z),
        sgnf(g0.w * (__high2float(hp[1]) - m0.w) * r0.w + b0.w));
    __half2 p2 = __floats2half2_rn(
        sgnf(g1.x * (__low2float(hp[2]) - m1.x) * r1.x + b1.x),
        sgnf(g1.y * (__high2float(hp[2]) - m1.y) * r1.y + b1.y));
    __half2 p3 = __floats2half2_rn(
        sgnf(g1.z * (__low2float(hp[3]) - m1.z) * r1.z + b1.z),
        sgnf(g1.w * (__high2float(hp[3]) - m1.w) * r1.w + b1.w));
    uint4 v;
    v.x = *(uint32_t*)&p0; v.y = *(uint32_t*)&p1;
    v.z = *(uint32_t*)&p2; v.w = *(uint32_t*)&p3;
    *(uint4*)&a[e0] = v;
}

// ---------------- host orchestration --------------------------------------------
extern "C" void kernel_launch(void* const* d_in, const int* in_sizes, int n_in,
                              void* d_out, int out_size) {
    const float* x     = (const float*)d_in[0];
    const float* W1    = (const float*)d_in[2];
    const float* g1    = (const float*)d_in[3];
    const float* b1    = (const float*)d_in[4];
    const float* W2    = (const float*)d_in[5];
    const float* g2    = (const float*)d_in[6];
    const float* b2    = (const float*)d_in[7];
    const float* W3    = (const float*)d_in[8];
    const float* g3    = (const float*)d_in[9];
    const float* b3    = (const float*)d_in[10];
    const float* W4    = (const float*)d_in[11];
    const float* scale = (const float*)d_in[12];
    float* y = (float*)d_out;

    __half *xt2, *w1b, *wb, *a;
    float *h, *mu, *rs, *ps2, *pq2;
    cudaGetSymbolAddress((void**)&xt2, g_xt2);
    cudaGetSymbolAddress((void**)&w1b, g_w1b);
    cudaGetSymbolAddress((void**)&wb,  g_wb);
    cudaGetSymbolAddress((void**)&h,   g_h);
    cudaGetSymbolAddress((void**)&a,   g_a);
    cudaGetSymbolAddress((void**)&mu,  g_mu);
    cudaGetSymbolAddress((void**)&rs,  g_rs);
    cudaGetSymbolAddress((void**)&ps2, g_ps2);
    cudaGetSymbolAddress((void**)&pq2, g_pq2);
    __half* h16 = (__half*)h;
    __half* w2b = wb;
    __half* w3b = wb + (size_t)HD * HD;
    __half* w4b = wb + (size_t)2 * HD * HD;

    cudaFuncSetAttribute(gemm_l1,     cudaFuncAttributeMaxDynamicSharedMemorySize, SMEM_L1);
    cudaFuncSetAttribute(gemm_f16<0>, cudaFuncAttributeMaxDynamicSharedMemorySize, SMEM_F16);
    cudaFuncSetAttribute(gemm_f16<2>, cudaFuncAttributeMaxDynamicSharedMemorySize, SMEM_F16);
    cudaFuncSetAttribute(combine_l4,  cudaFuncAttributeMaxDynamicSharedMemorySize, SMEM_CMB);

    // prep (W2/W3/W4 binarization folded into gemm_l1)
    transpose_split2<<<dim3(TD / 32, FIN / 32, NB), dim3(32, 8)>>>(x, xt2);
    binw1<<<(HD * FIN / 8 + 255) / 256, 256>>>(W1, w1b);

    dim3 blk(256);
    dim3 gridSign((unsigned)(((size_t)MR * HD / 8 + 255) / 256));
    dim3 gGemm(HD / BN, MR / BM);       // (16, 64)
    dim3 gGemm4(FIN / BN, MR / BM, 2);  // (4, 64, 2) split-K
    dim3 gComb(FIN / 128, MR / 128);    // (4, 64)

    // layer 1 (f16 2-way split, f32 accum, K=1024, fused stats + weight binarize)
    gemm_l1<<<gGemm, blk, SMEM_L1>>>(xt2, w1b, h, HD, 1024, ps2, pq2, W2, W3, W4, wb);
    stats_final128<<<dim3(HD / 256), blk>>>(ps2, pq2, mu, rs);
    sign_act_f32<<<gridSign, blk>>>(h, mu, rs, g1, b1, a);

    // layer 2
    gemm_f16<0><<<gGemm, blk, SMEM_F16>>>(a, w2b, h16, HD, HD, nullptr, ps2, pq2);
    stats_final128<<<dim3(HD / 256), blk>>>(ps2, pq2, mu, rs);
    sign_act_f16<<<gridSign, blk>>>(h16, mu, rs, g2, b2, a);

    // layer 3
    gemm_f16<0><<<gGemm, blk, SMEM_F16>>>(a, w3b, h16, HD, HD, nullptr, ps2, pq2);
    stats_final128<<<dim3(HD / 256), blk>>>(ps2, pq2, mu, rs);
    sign_act_f16<<<gridSign, blk>>>(h16, mu, rs, g3, b3, a);

    // layer 4: split-K=2 partials into h16 scratch, then exact combine
    gemm_f16<2><<<gGemm4, blk, SMEM_F16>>>(a, w4b, h16, FIN, HD, nullptr, nullptr, nullptr);
    combine_l4<<<gComb, blk, SMEM_CMB>>>(h16, y, scale);
}

// round 16
// speedup vs baseline: 1.0352x; 1.0352x over previous
#include <cuda_runtime.h>
#include <cuda_fp16.h>
#include <cstdint>
#include <cstddef>

#define NB   16
#define FIN  512
#define TD   512
#define MR   8192
#define HD   2048

#define BM   128
#define BN   128
#define LDROW 144
#define TILEB (128 * LDROW)              // 18432 B
#define STAGEB (2 * TILEB)               // 36864 B
#define SMEM_L1 (3 * STAGEB)             // 110592 B (gemm_l1: 3 stages, 2 CTAs)
#define SMEM_F16 (2 * STAGEB)            // 73728 B  (gemm_f16: 2 stages, 3 CTAs)

// ---------------- scratch ----------------------------------------------------
__device__ __half g_xt2[(size_t)MR * 1024];
__device__ __half g_w1b[(size_t)HD * 1024];
__device__ __half g_wb[(size_t)2 * HD * HD + (size_t)FIN * HD];
__device__ float  g_h[(size_t)MR * HD];
__device__ __half g_a[(size_t)MR * HD];
__device__ float g_mu[HD], g_rs[HD];
__device__ float g_ps2[128 * HD], g_pq2[128 * HD];

__device__ __forceinline__ float sgnf(float v) {
    return (v > 0.f) ? 1.f : ((v < 0.f) ? -1.f : 0.f);
}
__device__ __forceinline__ uint32_t smem_u32(const void* p) {
    return (uint32_t)__cvta_generic_to_shared(p);
}
__device__ __forceinline__ void cp16(uint32_t dst, const void* src) {
    asm volatile("cp.async.cg.shared.global [%0], [%1], 16;" :: "r"(dst), "l"(src));
}
__device__ __forceinline__ void ldsm4(uint32_t& r0, uint32_t& r1, uint32_t& r2, uint32_t& r3,
                                      uint32_t a) {
    asm volatile("ldmatrix.sync.aligned.m8n8.x4.shared.b16 {%0,%1,%2,%3}, [%4];"
                 : "=r"(r0), "=r"(r1), "=r"(r2), "=r"(r3) : "r"(a));
}
__device__ __forceinline__ void mma_f16_f32(float* c, const uint32_t* a, const uint32_t* b) {
    asm volatile("mma.sync.aligned.m16n8k16.row.col.f32.f16.f16.f32 "
                 "{%0,%1,%2,%3},{%4,%5,%6,%7},{%8,%9},{%0,%1,%2,%3};"
                 : "+f"(c[0]), "+f"(c[1]), "+f"(c[2]), "+f"(c[3])
                 : "r"(a[0]), "r"(a[1]), "r"(a[2]), "r"(a[3]), "r"(b[0]), "r"(b[1]));
}
__device__ __forceinline__ void mma_f16_f16(uint32_t* c, const uint32_t* a, const uint32_t* b) {
    asm volatile("mma.sync.aligned.m16n8k16.row.col.f16.f16.f16.f16 "
                 "{%0,%1},{%2,%3,%4,%5},{%6,%7},{%0,%1};"
                 : "+r"(c[0]), "+r"(c[1])
                 : "r"(a[0]), "r"(a[1]), "r"(a[2]), "r"(a[3]), "r"(b[0]), "r"(b[1]));
}

// ---------------- tile loader: 128 rows x 128B of K per stage -------------------
__device__ __forceinline__ void load_stage(
    const char* __restrict__ A, const char* __restrict__ B,
    size_t Kb, int bm, int bn, uint32_t smbase, int tid, int stage, int kc)
{
    uint32_t sA = smbase + stage * STAGEB;
    uint32_t sB = sA + TILEB;
    const char* gA = A + (size_t)bm * Kb + (size_t)kc * 128;
    const char* gB = B + (size_t)bn * Kb + (size_t)kc * 128;
#pragma unroll
    for (int i = 0; i < 4; i++) {
        int idx = tid + i * 256;
        int r = idx >> 3, c = idx & 7;
        cp16(sA + r * LDROW + c * 16, gA + (size_t)r * Kb + c * 16);
    }
#pragma unroll
    for (int i = 0; i < 4; i++) {
        int idx = tid + i * 256;
        int r = idx >> 3, c = idx & 7;
        cp16(sB + r * LDROW + c * 16, gB + (size_t)r * Kb + c * 16);
    }
    asm volatile("cp.async.commit_group;" ::: "memory");
}

// ---------------- f16-in / f32-acc GEMM (layer 1) + fused stats -----------------
__global__ void __launch_bounds__(256, 2)
gemm_l1(const __half* __restrict__ A, const __half* __restrict__ B,
        float* __restrict__ C, int N, int K,
        float* __restrict__ ps2, float* __restrict__ pq2)
{
    extern __shared__ char smraw[];
    const uint32_t smbase = smem_u32(smraw);
    const int tid = threadIdx.x, wid = tid >> 5, lid = tid & 31;
    const int bm = blockIdx.y * BM, bn = blockIdx.x * BN;
    const int NC = K / 64;
    const int wm = (wid & 1) * 64, wn = (wid >> 1) * 32;
    const int lr = ((lid >> 3) & 1) * 8 + (lid & 7);
    const int lc = (lid >> 4) * 8;
    const size_t Kb = (size_t)K * 2;

    float acc[4][4][4];
#pragma unroll
    for (int i = 0; i < 4; i++)
#pragma unroll
        for (int j = 0; j < 4; j++)
#pragma unroll
            for (int q = 0; q < 4; q++) acc[i][j][q] = 0.f;

    load_stage((const char*)A, (const char*)B, Kb, bm, bn, smbase, tid, 0, 0);
    load_stage((const char*)A, (const char*)B, Kb, bm, bn, smbase, tid, 1, 1);

    int st = 0;
    for (int kc = 0; kc < NC; ++kc) {
        asm volatile("cp.async.wait_group 1;" ::: "memory");
        __syncthreads();
        const uint32_t aBase = smbase + st * STAGEB;
        const uint32_t bBase = aBase + TILEB;
#pragma unroll
        for (int ks = 0; ks < 4; ++ks) {
            uint32_t a[4][4];
#pragma unroll
            for (int i = 0; i < 4; i++)
                ldsm4(a[i][0], a[i][1], a[i][2], a[i][3],
                      aBase + (uint32_t)(wm + i * 16 + lr) * LDROW
                            + (uint32_t)(ks * 16 + lc) * 2);
            uint32_t b[4][2];
#pragma unroll
            for (int jj = 0; jj < 2; jj++) {
                uint32_t r0, r1, r2, r3;
                ldsm4(r0, r1, r2, r3,
                      bBase + (uint32_t)(wn + jj * 16 + lr) * LDROW
                            + (uint32_t)(ks * 16 + lc) * 2);
                b[jj * 2 + 0][0] = r0; b[jj * 2 + 0][1] = r2;
                b[jj * 2 + 1][0] = r1; b[jj * 2 + 1][1] = r3;
            }
#pragma unroll
            for (int i = 0; i < 4; i++)
#pragma unroll
                for (int j = 0; j < 4; j++)
                    mma_f16_f32(acc[i][j], a[i], b[j]);
        }
        int nk = kc + 2;
        if (nk < NC) {
            int nst = st + 2; if (nst >= 3) nst -= 3;
            load_stage((const char*)A, (const char*)B, Kb, bm, bn, smbase, tid, nst, nk);
        } else
            asm volatile("cp.async.commit_group;" ::: "memory");
        if (++st == 3) st = 0;
    }

    const int row0 = lid >> 2, col0 = (lid & 3) * 2;
#pragma unroll
    for (int i = 0; i < 4; i++)
#pragma unroll
        for (int j = 0; j < 4; j++) {
            int m0 = bm + wm + i * 16 + row0;
            int n0 = bn + wn + j * 8 + col0;
            *(float2*)&C[(size_t)m0 * N + n0]       = make_float2(acc[i][j][0], acc[i][j][1]);
            *(float2*)&C[(size_t)(m0 + 8) * N + n0] = make_float2(acc[i][j][2], acc[i][j][3]);
        }
    // fused per-warp column stats
#pragma unroll
    for (int j = 0; j < 4; j++) {
        float s0 = 0.f, s1 = 0.f, q0 = 0.f, q1 = 0.f;
#pragma unroll
        for (int i = 0; i < 4; i++) {
            float a0 = acc[i][j][0], a1 = acc[i][j][2];
            float b0 = acc[i][j][1], b1 = acc[i][j][3];
            s0 += a0 + a1;  q0 += a0 * a0 + a1 * a1;
            s1 += b0 + b1;  q1 += b0 * b0 + b1 * b1;
        }
#pragma unroll
        for (int d = 4; d < 32; d <<= 1) {
            s0 += __shfl_xor_sync(0xFFFFFFFFu, s0, d);
            s1 += __shfl_xor_sync(0xFFFFFFFFu, s1, d);
            q0 += __shfl_xor_sync(0xFFFFFFFFu, q0, d);
            q1 += __shfl_xor_sync(0xFFFFFFFFu, q1, d);
        }
        if (lid < 4) {
            int prow = (int)blockIdx.y * 2 + (wid & 1);
            int col  = bn + wn + j * 8 + (lid & 3) * 2;
            *(float2*)&ps2[(size_t)prow * HD + col] = make_float2(s0, s1);
            *(float2*)&pq2[(size_t)prow * HD + col] = make_float2(q0, q1);
        }
    }
}

// ---------------- f16/f16 GEMM (layers 2/3/4): 2 stages, 3 CTAs/SM -------------
template <int EPI>
__global__ void __launch_bounds__(256, 3)
gemm_f16(const __half* __restrict__ A, const __half* __restrict__ B,
         void* __restrict__ Cv, int N, int K, const float* __restrict__ scale,
         float* __restrict__ ps2, float* __restrict__ pq2)
{
    extern __shared__ char smraw[];
    const uint32_t smbase = smem_u32(smraw);
    const int tid = threadIdx.x, wid = tid >> 5, lid = tid & 31;
    const int bm = blockIdx.y * BM, bn = blockIdx.x * BN;
    const int NC = K / 64;
    const int wm = (wid & 1) * 64, wn = (wid >> 1) * 32;
    const int lr = ((lid >> 3) & 1) * 8 + (lid & 7);
    const int lc = (lid >> 4) * 8;
    const size_t Kb = (size_t)K * 2;

    uint32_t acc[4][4][2];
#pragma unroll
    for (int i = 0; i < 4; i++)
#pragma unroll
        for (int j = 0; j < 4; j++) { acc[i][j][0] = 0u; acc[i][j][1] = 0u; }

    load_stage((const char*)A, (const char*)B, Kb, bm, bn, smbase, tid, 0, 0);

    int st = 0;
    for (int kc = 0; kc < NC; ++kc) {
        asm volatile("cp.async.wait_group 0;" ::: "memory");
        __syncthreads();
        if (kc + 1 < NC)
            load_stage((const char*)A, (const char*)B, Kb, bm, bn, smbase, tid, st ^ 1, kc + 1);
        const uint32_t aBase = smbase + st * STAGEB;
        const uint32_t bBase = aBase + TILEB;
#pragma unroll
        for (int ks = 0; ks < 4; ++ks) {
            uint32_t a[4][4];
#pragma unroll
            for (int i = 0; i < 4; i++)
                ldsm4(a[i][0], a[i][1], a[i][2], a[i][3],
                      aBase + (uint32_t)(wm + i * 16 + lr) * LDROW
                            + (uint32_t)(ks * 16 + lc) * 2);
            uint32_t b[4][2];
#pragma unroll
            for (int jj = 0; jj < 2; jj++) {
                uint32_t r0, r1, r2, r3;
                ldsm4(r0, r1, r2, r3,
                      bBase + (uint32_t)(wn + jj * 16 + lr) * LDROW
                            + (uint32_t)(ks * 16 + lc) * 2);
                b[jj * 2 + 0][0] = r0; b[jj * 2 + 0][1] = r2;
                b[jj * 2 + 1][0] = r1; b[jj * 2 + 1][1] = r3;
            }
#pragma unroll
            for (int i = 0; i < 4; i++)
#pragma unroll
                for (int j = 0; j < 4; j++)
                    mma_f16_f16(acc[i][j], a[i], b[j]);
        }
        st ^= 1;
    }

    const int row0 = lid >> 2, col0 = (lid & 3) * 2;
    if (EPI == 0) {
        __half* C = (__half*)Cv;
#pragma unroll
        for (int i = 0; i < 4; i++)
#pragma unroll
            for (int j = 0; j < 4; j++) {
                int m0 = bm + wm + i * 16 + row0;
                int n0 = bn + wn + j * 8 + col0;
                *(uint32_t*)&C[(size_t)m0 * N + n0]       = acc[i][j][0];
                *(uint32_t*)&C[(size_t)(m0 + 8) * N + n0] = acc[i][j][1];
            }
#pragma unroll
        for (int j = 0; j < 4; j++) {
            float s0 = 0.f, s1 = 0.f, q0 = 0.f, q1 = 0.f;
#pragma unroll
            for (int i = 0; i < 4; i++) {
                __half2 v0 = *(__half2*)&acc[i][j][0];
                __half2 v1 = *(__half2*)&acc[i][j][1];
                float a0 = __low2float(v0), b0 = __high2float(v0);
                float a1 = __low2float(v1), b1 = __high2float(v1);
                s0 += a0 + a1;  q0 += a0 * a0 + a1 * a1;
                s1 += b0 + b1;  q1 += b0 * b0 + b1 * b1;
            }
#pragma unroll
            for (int d = 4; d < 32; d <<= 1) {
                s0 += __shfl_xor_sync(0xFFFFFFFFu, s0, d);
                s1 += __shfl_xor_sync(0xFFFFFFFFu, s1, d);
                q0 += __shfl_xor_sync(0xFFFFFFFFu, q0, d);
                q1 += __shfl_xor_sync(0xFFFFFFFFu, q1, d);
            }
            if (lid < 4) {
                int prow = (int)blockIdx.y * 2 + (wid & 1);
                int col  = bn + wn + j * 8 + (lid & 3) * 2;
                *(float2*)&ps2[(size_t)prow * HD + col] = make_float2(s0, s1);
                *(float2*)&pq2[(size_t)prow * HD + col] = make_float2(q0, q1);
            }
        }
    } else {
        float* trans = (float*)smraw;
        __syncthreads();
#pragma unroll
        for (int j = 0; j < 4; j++) {
            int n0 = wn + j * 8 + col0;
            float s0 = scale[bn + n0], s1 = scale[bn + n0 + 1];
#pragma unroll
            for (int i = 0; i < 4; i++) {
                int t0 = wm + i * 16 + row0;
                __half2 v0 = *(__half2*)&acc[i][j][0];
                __half2 v1 = *(__half2*)&acc[i][j][1];
                trans[n0 * 132 + t0]           = __low2float(v0) * s0;
                trans[(n0 + 1) * 132 + t0]     = __high2float(v0) * s1;
                trans[n0 * 132 + t0 + 8]       = __low2float(v1) * s0;
                trans[(n0 + 1) * 132 + t0 + 8] = __high2float(v1) * s1;
            }
        }
        __syncthreads();
        float* y = (float*)Cv;
        const int b0 = bm >> 9;
        const int tb = bm & 511;
        const int n = tid >> 1, half = tid & 1;
        float* yp = y + ((size_t)b0 * FIN + bn + n) * TD + tb + half * 64;
        const float* sp = trans + n * 132 + half * 64;
#pragma unroll
        for (int k = 0; k < 16; k++)
            *(float4*)&yp[k * 4] = *(const float4*)&sp[k * 4];
    }
}

// ---------------- prep kernels -------------------------------------------------
__global__ void transpose_split2(const float* __restrict__ x, __half* __restrict__ xt2) {
    __shared__ float tile[32][33];
    int n = blockIdx.z, t0 = blockIdx.x * 32, f0 = blockIdx.y * 32;
    const float* xp = x + (size_t)n * FIN * TD;
#pragma unroll
    for (int i = 0; i < 4; i++) {
        int f = f0 + threadIdx.y + i * 8;
        tile[threadIdx.y + i * 8][threadIdx.x] = xp[(size_t)f * TD + t0 + threadIdx.x];
    }
    __syncthreads();
#pragma unroll
    for (int i = 0; i < 4; i++) {
        int t = t0 + threadIdx.y + i * 8;
        int f = f0 + threadIdx.x;
        float v = tile[threadIdx.x][threadIdx.y + i * 8];
        __half hi = __float2half_rn(v);
        float r1 = v - __half2float(hi);
        __half lo = __float2half_rn(r1);
        size_t row = (size_t)((size_t)n * TD + t) * 1024;
        xt2[row + f] = hi;
        xt2[row + 512 + f] = lo;
    }
}

__global__ void binw_all(const float* __restrict__ W2, const float* __restrict__ W3,
                         const float* __restrict__ W4, __half* __restrict__ o) {
    const int C2 = HD * HD / 8, C3 = 2 * C2, C4 = C3 + FIN * HD / 8;
    int i = blockIdx.x * 256 + threadIdx.x;
    if (i >= C4) return;
    const float* src;
    size_t off;
    if (i < C2)      { src = W2; off = (size_t)i * 8; }
    else if (i < C3) { src = W3; off = (size_t)(i - C2) * 8; }
    else             { src = W4; off = (size_t)(i - C3) * 8; }
    float4 w0 = *(const float4*)&src[off];
    float4 w1 = *(const float4*)&src[off + 4];
    __half2 p0 = __floats2half2_rn(sgnf(w0.x), sgnf(w0.y));
    __half2 p1 = __floats2half2_rn(sgnf(w0.z), sgnf(w0.w));
    __half2 p2 = __floats2half2_rn(sgnf(w1.x), sgnf(w1.y));
    __half2 p3 = __floats2half2_rn(sgnf(w1.z), sgnf(w1.w));
    uint4 v;
    v.x = *(uint32_t*)&p0; v.y = *(uint32_t*)&p1;
    v.z = *(uint32_t*)&p2; v.w = *(uint32_t*)&p3;
    *(uint4*)&o[(size_t)i * 8] = v;
}
__global__ void binw1(const float* __restrict__ W1, __half* __restrict__ o) {
    int i = blockIdx.x * 256 + threadIdx.x;
    if (i >= HD * FIN / 8) return;
    float4 w0 = *(const float4*)&W1[(size_t)i * 8];
    float4 w1 = *(const float4*)&W1[(size_t)i * 8 + 4];
    int row = (i * 8) >> 9, k = (i * 8) & 511;
    __half2 p0 = __floats2half2_rn(sgnf(w0.x), sgnf(w0.y));
    __half2 p1 = __floats2half2_rn(sgnf(w0.z), sgnf(w0.w));
    __half2 p2 = __floats2half2_rn(sgnf(w1.x), sgnf(w1.y));
    __half2 p3 = __floats2half2_rn(sgnf(w1.z), sgnf(w1.w));
    uint4 v;
    v.x = *(uint32_t*)&p0; v.y = *(uint32_t*)&p1;
    v.z = *(uint32_t*)&p2; v.w = *(uint32_t*)&p3;
    size_t base = (size_t)row * 1024 + k;
    *(uint4*)&o[base] = v;
    *(uint4*)&o[base + 512] = v;
}

// ---------------- BN stats: parallel 128-partial reduce --------------------------
// grid HD/32, block 256 = 32 cols x 8 lanes; lane l sums p = l*16 .. l*16+15,
// then fixed-order lane combine (deterministic).
__global__ void stats_final128(const float* __restrict__ ps2, const float* __restrict__ pq2,
                               float* __restrict__ mu, float* __restrict__ rs) {
    const int c = threadIdx.x & 31, lane = threadIdx.x >> 5;
    const int col = blockIdx.x * 32 + c;
    const int p0 = lane * 16;
    float s = 0.f, sq = 0.f;
#pragma unroll
    for (int p = 0; p < 16; p++) {
        s  += ps2[(size_t)(p0 + p) * HD + col];
        sq += pq2[(size_t)(p0 + p) * HD + col];
    }
    __shared__ float ss[8][33], sv[8][33];
    ss[lane][c] = s; sv[lane][c] = sq;
    __syncthreads();
    if (lane == 0) {
        float ts = 0.f, tq = 0.f;
#pragma unroll
        for (int l = 0; l < 8; l++) { ts += ss[l][c]; tq += sv[l][c]; }
        float m = ts * (1.f / MR);
        float var = tq * (1.f / MR) - m * m;
        if (var < 0.f) var = 0.f;
        mu[col] = m;
        rs[col] = rsqrtf(var + 1e-5f);
    }
}

// ---------------- sign activations (8 elems/thread) ------------------------------
__global__ void sign_act_f32(const float* __restrict__ h,
                             const float* __restrict__ mu, const float* __restrict__ rs,
                             const float* __restrict__ g, const float* __restrict__ b,
                             __half* __restrict__ a) {
    size_t i8 = (size_t)blockIdx.x * blockDim.x + threadIdx.x;
    size_t e0 = i8 * 8;
    if (e0 >= (size_t)MR * HD) return;
    int j = (int)(e0 % HD);
    float4 h0 = *(const float4*)&h[e0];
    float4 h1 = *(const float4*)&h[e0 + 4];
    float4 m0 = *(const float4*)&mu[j], m1 = *(const float4*)&mu[j + 4];
    float4 r0 = *(const float4*)&rs[j], r1 = *(const float4*)&rs[j + 4];
    float4 g0 = *(const float4*)&g[j],  g1 = *(const float4*)&g[j + 4];
    float4 b0 = *(const float4*)&b[j],  b1 = *(const float4*)&b[j + 4];
    __half2 p0 = __floats2half2_rn(sgnf(g0.x * (h0.x - m0.x) * r0.x + b0.x),
                                   sgnf(g0.y * (h0.y - m0.y) * r0.y + b0.y));
    __half2 p1 = __floats2half2_rn(sgnf(g0.z * (h0.z - m0.z) * r0.z + b0.z),
                                   sgnf(g0.w * (h0.w - m0.w) * r0.w + b0.w));
    __half2 p2 = __floats2half2_rn(sgnf(g1.x * (h1.x - m1.x) * r1.x + b1.x),
                                   sgnf(g1.y * (h1.y - m1.y) * r1.y + b1.y));
    __half2 p3 = __floats2half2_rn(sgnf(g1.z * (h1.z - m1.z) * r1.z + b1.z),
                                   sgnf(g1.w * (h1.w - m1.w) * r1.w + b1.w));
    uint4 v;
    v.x = *(uint32_t*)&p0; v.y = *(uint32_t*)&p1;
    v.z = *(uint32_t*)&p2; v.w = *(uint32_t*)&p3;
    *(uint4*)&a[e0] = v;
}
__global__ void sign_act_f16(const __half* __restrict__ h,
                             const float* __restrict__ mu, const float* __restrict__ rs,
                             const float* __restrict__ g, const float* __restrict__ b,
                             __half* __restrict__ a) {
    size_t i8 = (size_t)blockIdx.x * blockDim.x + threadIdx.x;
    size_t e0 = i8 * 8;
    if (e0 >= (size_t)MR * HD) return;
    int j = (int)(e0 % HD);
    uint4 hv = *(const uint4*)&h[e0];
    const __half2* hp = (const __half2*)&hv;
    float4 m0 = *(const float4*)&mu[j], m1 = *(const float4*)&mu[j + 4];
    float4 r0 = *(const float4*)&rs[j], r1 = *(const float4*)&rs[j + 4];
    float4 g0 = *(const float4*)&g[j],  g1 = *(const float4*)&g[j + 4];
    float4 b0 = *(const float4*)&b[j],  b1 = *(const float4*)&b[j + 4];
    __half2 p0 = __floats2half2_rn(
        sgnf(g0.x * (__low2float(hp[0]) - m0.x) * r0.x + b0.x),
        sgnf(g0.y * (__high2float(hp[0]) - m0.y) * r0.y + b0.y));
    __half2 p1 = __floats2half2_rn(
        sgnf(g0.z * (__low2float(hp[1]) - m0.z) * r0.z + b0.z),
        sgnf(g0.w * (__high2float(hp[1]) - m0.w) * r0.w + b0.w));
    __half2 p2 = __floats2half2_rn(
        sgnf(g1.x * (__low2float(hp[2]) - m1.x) * r1.x + b1.x),
        sgnf(g1.y * (__high2float(hp[2]) - m1.y) * r1.y + b1.y));
    __half2 p3 = __floats2half2_rn(
        sgnf(g1.z * (__low2float(hp[3]) - m1.z) * r1.z + b1.z),
        sgnf(g1.w * (__high2float(hp[3]) - m1.w) * r1.w + b1.w));
    uint4 v;
    v.x = *(uint32_t*)&p0; v.y = *(uint32_t*)&p1;
    v.z = *(uint32_t*)&p2; v.w = *(uint32_t*)&p3;
    *(uint4*)&a[e0] = v;
}

// ---------------- host orchestration --------------------------------------------
extern "C" void kernel_launch(void* const* d_in, const int* in_sizes, int n_in,
                              void* d_out, int out_size) {
    const float* x     = (const float*)d_in[0];
    const float* W1    = (const float*)d_in[2];
    const float* g1    = (const float*)d_in[3];
    const float* b1    = (const float*)d_in[4];
    const float* W2    = (const float*)d_in[5];
    const float* g2    = (const float*)d_in[6];
    const float* b2    = (const float*)d_in[7];
    const float* W3    = (const float*)d_in[8];
    const float* g3    = (const float*)d_in[9];
    const float* b3    = (const float*)d_in[10];
    const float* W4    = (const float*)d_in[11];
    const float* scale = (const float*)d_in[12];
    float* y = (float*)d_out;

    __half *xt2, *w1b, *wb, *a;
    float *h, *mu, *rs, *ps2, *pq2;
    cudaGetSymbolAddress((void**)&xt2, g_xt2);
    cudaGetSymbolAddress((void**)&w1b, g_w1b);
    cudaGetSymbolAddress((void**)&wb,  g_wb);
    cudaGetSymbolAddress((void**)&h,   g_h);
    cudaGetSymbolAddress((void**)&a,   g_a);
    cudaGetSymbolAddress((void**)&mu,  g_mu);
    cudaGetSymbolAddress((void**)&rs,  g_rs);
    cudaGetSymbolAddress((void**)&ps2, g_ps2);
    cudaGetSymbolAddress((void**)&pq2, g_pq2);
    __half* h16 = (__half*)h;
    __half* w2b = wb;
    __half* w3b = wb + (size_t)HD * HD;
    __half* w4b = wb + (size_t)2 * HD * HD;

    cudaFuncSetAttribute(gemm_l1,     cudaFuncAttributeMaxDynamicSharedMemorySize, SMEM_L1);
    cudaFuncSetAttribute(gemm_f16<0>, cudaFuncAttributeMaxDynamicSharedMemorySize, SMEM_F16);
    cudaFuncSetAttribute(gemm_f16<1>, cudaFuncAttributeMaxDynamicSharedMemorySize, SMEM_F16);

    // prep
    transpose_split2<<<dim3(TD / 32, FIN / 32, NB), dim3(32, 8)>>>(x, xt2);
    binw1<<<(HD * FIN / 8 + 255) / 256, 256>>>(W1, w1b);
    {
        int chunks = (2 * HD * HD + FIN * HD) / 8;
        binw_all<<<(chunks + 255) / 256, 256>>>(W2, W3, W4, wb);
    }

    dim3 blk(256);
    dim3 gridSign((unsigned)(((size_t)MR * HD / 8 + 255) / 256));
    dim3 gridStats(HD / 32);
    dim3 gGemm(HD / BN, MR / BM);   // (16, 64)
    dim3 gGemm4(FIN / BN, MR / BM); // (4, 64)

    // layer 1 (f16 2-way split, f32 accum, K=1024, fused stats)
    gemm_l1<<<gGemm, blk, SMEM_L1>>>(xt2, w1b, h, HD, 1024, ps2, pq2);
    stats_final128<<<gridStats, blk>>>(ps2, pq2, mu, rs);
    sign_act_f32<<<gridSign, blk>>>(h, mu, rs, g1, b1, a);

    // layer 2
    gemm_f16<0><<<gGemm, blk, SMEM_F16>>>(a, w2b, h16, HD, HD, nullptr, ps2, pq2);
    stats_final128<<<gridStats, blk>>>(ps2, pq2, mu, rs);
    sign_act_f16<<<gridSign, blk>>>(h16, mu, rs, g2, b2, a);

    // layer 3
    gemm_f16<0><<<gGemm, blk, SMEM_F16>>>(a, w3b, h16, HD, HD, nullptr, ps2, pq2);
    stats_final128<<<gridStats, blk>>>(ps2, pq2, mu, rs);
    sign_act_f16<<<gridSign, blk>>>(h16, mu, rs, g3, b3, a);

    // layer 4
    gemm_f16<1><<<gGemm4, blk, SMEM_F16>>>(a, w4b, y, FIN, HD, scale, nullptr, nullptr);
}

// round 17
// speedup vs baseline: 1.0718x; 1.0354x over previous
#include <cuda_runtime.h>
#include <cuda_fp16.h>
#include <cstdint>
#include <cstddef>

#define NB   16
#define FIN  512
#define TD   512
#define MR   8192
#define HD   2048

#define BM   128
#define BN   128
#define LDROW 144
#define TILEB (128 * LDROW)              // 18432 B
#define STAGEB (2 * TILEB)               // 36864 B
#define SMEM_L1 (3 * STAGEB)             // 110592 B (gemm_l1: 3 stages, 2 CTAs)
#define SMEM_F16 (2 * STAGEB)            // 73728 B  (gemm_f16: 2 stages, 3 CTAs)

// ---------------- scratch ----------------------------------------------------
__device__ __half g_xt2[(size_t)MR * 1024];
__device__ __half g_w1b[(size_t)HD * 1024];
__device__ __half g_wb[(size_t)2 * HD * HD + (size_t)FIN * HD];
__device__ float  g_h[(size_t)MR * HD];
__device__ __half g_a[(size_t)MR * HD];
__device__ float g_mu[HD], g_rs[HD];
__device__ float g_ps2[128 * HD], g_pq2[128 * HD];

__device__ __forceinline__ float sgnf(float v) {
    return (v > 0.f) ? 1.f : ((v < 0.f) ? -1.f : 0.f);
}
__device__ __forceinline__ uint32_t smem_u32(const void* p) {
    return (uint32_t)__cvta_generic_to_shared(p);
}
__device__ __forceinline__ void cp16(uint32_t dst, const void* src) {
    asm volatile("cp.async.cg.shared.global [%0], [%1], 16;" :: "r"(dst), "l"(src));
}
__device__ __forceinline__ void ldsm4(uint32_t& r0, uint32_t& r1, uint32_t& r2, uint32_t& r3,
                                      uint32_t a) {
    asm volatile("ldmatrix.sync.aligned.m8n8.x4.shared.b16 {%0,%1,%2,%3}, [%4];"
                 : "=r"(r0), "=r"(r1), "=r"(r2), "=r"(r3) : "r"(a));
}
__device__ __forceinline__ void mma_f16_f32(float* c, const uint32_t* a, const uint32_t* b) {
    asm volatile("mma.sync.aligned.m16n8k16.row.col.f32.f16.f16.f32 "
                 "{%0,%1,%2,%3},{%4,%5,%6,%7},{%8,%9},{%0,%1,%2,%3};"
                 : "+f"(c[0]), "+f"(c[1]), "+f"(c[2]), "+f"(c[3])
                 : "r"(a[0]), "r"(a[1]), "r"(a[2]), "r"(a[3]), "r"(b[0]), "r"(b[1]));
}
__device__ __forceinline__ void mma_f16_f16(uint32_t* c, const uint32_t* a, const uint32_t* b) {
    asm volatile("mma.sync.aligned.m16n8k16.row.col.f16.f16.f16.f16 "
                 "{%0,%1},{%2,%3,%4,%5},{%6,%7},{%0,%1};"
                 : "+r"(c[0]), "+r"(c[1])
                 : "r"(a[0]), "r"(a[1]), "r"(a[2]), "r"(a[3]), "r"(b[0]), "r"(b[1]));
}

// ---------------- tile loader: 128 rows x 128B of K per stage -------------------
__device__ __forceinline__ void load_stage(
    const char* __restrict__ A, const char* __restrict__ B,
    size_t Kb, int bm, int bn, uint32_t smbase, int tid, int stage, int kc)
{
    uint32_t sA = smbase + stage * STAGEB;
    uint32_t sB = sA + TILEB;
    const char* gA = A + (size_t)bm * Kb + (size_t)kc * 128;
    const char* gB = B + (size_t)bn * Kb + (size_t)kc * 128;
#pragma unroll
    for (int i = 0; i < 4; i++) {
        int idx = tid + i * 256;
        int r = idx >> 3, c = idx & 7;
        cp16(sA + r * LDROW + c * 16, gA + (size_t)r * Kb + c * 16);
    }
#pragma unroll
    for (int i = 0; i < 4; i++) {
        int idx = tid + i * 256;
        int r = idx >> 3, c = idx & 7;
        cp16(sB + r * LDROW + c * 16, gB + (size_t)r * Kb + c * 16);
    }
    asm volatile("cp.async.commit_group;" ::: "memory");
}

// ---------------- f16-in / f32-acc GEMM (layer 1) + fused stats -----------------
__global__ void __launch_bounds__(256, 2)
gemm_l1(const __half* __restrict__ A, const __half* __restrict__ B,
        float* __restrict__ C, int N, int K,
        float* __restrict__ ps2, float* __restrict__ pq2)
{
    extern __shared__ char smraw[];
    const uint32_t smbase = smem_u32(smraw);
    const int tid = threadIdx.x, wid = tid >> 5, lid = tid & 31;
    const int bm = blockIdx.y * BM, bn = blockIdx.x * BN;
    const int NC = K / 64;
    const int wm = (wid & 1) * 64, wn = (wid >> 1) * 32;
    const int lr = ((lid >> 3) & 1) * 8 + (lid & 7);
    const int lc = (lid >> 4) * 8;
    const size_t Kb = (size_t)K * 2;

    float acc[4][4][4];
#pragma unroll
    for (int i = 0; i < 4; i++)
#pragma unroll
        for (int j = 0; j < 4; j++)
#pragma unroll
            for (int q = 0; q < 4; q++) acc[i][j][q] = 0.f;

    load_stage((const char*)A, (const char*)B, Kb, bm, bn, smbase, tid, 0, 0);
    load_stage((const char*)A, (const char*)B, Kb, bm, bn, smbase, tid, 1, 1);

    int st = 0;
    for (int kc = 0; kc < NC; ++kc) {
        asm volatile("cp.async.wait_group 1;" ::: "memory");
        __syncthreads();
        const uint32_t aBase = smbase + st * STAGEB;
        const uint32_t bBase = aBase + TILEB;
#pragma unroll
        for (int ks = 0; ks < 4; ++ks) {
            uint32_t a[4][4];
#pragma unroll
            for (int i = 0; i < 4; i++)
                ldsm4(a[i][0], a[i][1], a[i][2], a[i][3],
                      aBase + (uint32_t)(wm + i * 16 + lr) * LDROW
                            + (uint32_t)(ks * 16 + lc) * 2);
            uint32_t b[4][2];
#pragma unroll
            for (int jj = 0; jj < 2; jj++) {
                uint32_t r0, r1, r2, r3;
                ldsm4(r0, r1, r2, r3,
                      bBase + (uint32_t)(wn + jj * 16 + lr) * LDROW
                            + (uint32_t)(ks * 16 + lc) * 2);
                b[jj * 2 + 0][0] = r0; b[jj * 2 + 0][1] = r2;
                b[jj * 2 + 1][0] = r1; b[jj * 2 + 1][1] = r3;
            }
#pragma unroll
            for (int i = 0; i < 4; i++)
#pragma unroll
                for (int j = 0; j < 4; j++)
                    mma_f16_f32(acc[i][j], a[i], b[j]);
        }
        int nk = kc + 2;
        if (nk < NC) {
            int nst = st + 2; if (nst >= 3) nst -= 3;
            load_stage((const char*)A, (const char*)B, Kb, bm, bn, smbase, tid, nst, nk);
        } else
            asm volatile("cp.async.commit_group;" ::: "memory");
        if (++st == 3) st = 0;
    }

    const int row0 = lid >> 2, col0 = (lid & 3) * 2;
#pragma unroll
    for (int i = 0; i < 4; i++)
#pragma unroll
        for (int j = 0; j < 4; j++) {
            int m0 = bm + wm + i * 16 + row0;
            int n0 = bn + wn + j * 8 + col0;
            *(float2*)&C[(size_t)m0 * N + n0]       = make_float2(acc[i][j][0], acc[i][j][1]);
            *(float2*)&C[(size_t)(m0 + 8) * N + n0] = make_float2(acc[i][j][2], acc[i][j][3]);
        }
    // fused per-warp column stats
#pragma unroll
    for (int j = 0; j < 4; j++) {
        float s0 = 0.f, s1 = 0.f, q0 = 0.f, q1 = 0.f;
#pragma unroll
        for (int i = 0; i < 4; i++) {
            float a0 = acc[i][j][0], a1 = acc[i][j][2];
            float b0 = acc[i][j][1], b1 = acc[i][j][3];
            s0 += a0 + a1;  q0 += a0 * a0 + a1 * a1;
            s1 += b0 + b1;  q1 += b0 * b0 + b1 * b1;
        }
#pragma unroll
        for (int d = 4; d < 32; d <<= 1) {
            s0 += __shfl_xor_sync(0xFFFFFFFFu, s0, d);
            s1 += __shfl_xor_sync(0xFFFFFFFFu, s1, d);
            q0 += __shfl_xor_sync(0xFFFFFFFFu, q0, d);
            q1 += __shfl_xor_sync(0xFFFFFFFFu, q1, d);
        }
        if (lid < 4) {
            int prow = (int)blockIdx.y * 2 + (wid & 1);
            int col  = bn + wn + j * 8 + (lid & 3) * 2;
            *(float2*)&ps2[(size_t)prow * HD + col] = make_float2(s0, s1);
            *(float2*)&pq2[(size_t)prow * HD + col] = make_float2(q0, q1);
        }
    }
}

// ---------------- f16/f16 GEMM (layers 2/3/4): 2 stages, 3 CTAs/SM -------------
template <int EPI>
__global__ void __launch_bounds__(256, 3)
gemm_f16(const __half* __restrict__ A, const __half* __restrict__ B,
         void* __restrict__ Cv, int N, int K, const float* __restrict__ scale,
         float* __restrict__ ps2, float* __restrict__ pq2)
{
    extern __shared__ char smraw[];
    const uint32_t smbase = smem_u32(smraw);
    const int tid = threadIdx.x, wid = tid >> 5, lid = tid & 31;
    const int bm = blockIdx.y * BM, bn = blockIdx.x * BN;
    const int NC = K / 64;
    const int wm = (wid & 1) * 64, wn = (wid >> 1) * 32;
    const int lr = ((lid >> 3) & 1) * 8 + (lid & 7);
    const int lc = (lid >> 4) * 8;
    const size_t Kb = (size_t)K * 2;

    uint32_t acc[4][4][2];
#pragma unroll
    for (int i = 0; i < 4; i++)
#pragma unroll
        for (int j = 0; j < 4; j++) { acc[i][j][0] = 0u; acc[i][j][1] = 0u; }

    load_stage((const char*)A, (const char*)B, Kb, bm, bn, smbase, tid, 0, 0);

    int st = 0;
    for (int kc = 0; kc < NC; ++kc) {
        asm volatile("cp.async.wait_group 0;" ::: "memory");
        __syncthreads();
        if (kc + 1 < NC)
            load_stage((const char*)A, (const char*)B, Kb, bm, bn, smbase, tid, st ^ 1, kc + 1);
        const uint32_t aBase = smbase + st * STAGEB;
        const uint32_t bBase = aBase + TILEB;
#pragma unroll
        for (int ks = 0; ks < 4; ++ks) {
            uint32_t a[4][4];
#pragma unroll
            for (int i = 0; i < 4; i++)
                ldsm4(a[i][0], a[i][1], a[i][2], a[i][3],
                      aBase + (uint32_t)(wm + i * 16 + lr) * LDROW
                            + (uint32_t)(ks * 16 + lc) * 2);
            uint32_t b[4][2];
#pragma unroll
            for (int jj = 0; jj < 2; jj++) {
                uint32_t r0, r1, r2, r3;
                ldsm4(r0, r1, r2, r3,
                      bBase + (uint32_t)(wn + jj * 16 + lr) * LDROW
                            + (uint32_t)(ks * 16 + lc) * 2);
                b[jj * 2 + 0][0] = r0; b[jj * 2 + 0][1] = r2;
                b[jj * 2 + 1][0] = r1; b[jj * 2 + 1][1] = r3;
            }
#pragma unroll
            for (int i = 0; i < 4; i++)
#pragma unroll
                for (int j = 0; j < 4; j++)
                    mma_f16_f16(acc[i][j], a[i], b[j]);
        }
        st ^= 1;
    }

    const int row0 = lid >> 2, col0 = (lid & 3) * 2;
    if (EPI == 0) {
        __half* C = (__half*)Cv;
#pragma unroll
        for (int i = 0; i < 4; i++)
#pragma unroll
            for (int j = 0; j < 4; j++) {
                int m0 = bm + wm + i * 16 + row0;
                int n0 = bn + wn + j * 8 + col0;
                *(uint32_t*)&C[(size_t)m0 * N + n0]       = acc[i][j][0];
                *(uint32_t*)&C[(size_t)(m0 + 8) * N + n0] = acc[i][j][1];
            }
#pragma unroll
        for (int j = 0; j < 4; j++) {
            float s0 = 0.f, s1 = 0.f, q0 = 0.f, q1 = 0.f;
#pragma unroll
            for (int i = 0; i < 4; i++) {
                __half2 v0 = *(__half2*)&acc[i][j][0];
                __half2 v1 = *(__half2*)&acc[i][j][1];
                float a0 = __low2float(v0), b0 = __high2float(v0);
                float a1 = __low2float(v1), b1 = __high2float(v1);
                s0 += a0 + a1;  q0 += a0 * a0 + a1 * a1;
                s1 += b0 + b1;  q1 += b0 * b0 + b1 * b1;
            }
#pragma unroll
            for (int d = 4; d < 32; d <<= 1) {
                s0 += __shfl_xor_sync(0xFFFFFFFFu, s0, d);
                s1 += __shfl_xor_sync(0xFFFFFFFFu, s1, d);
                q0 += __shfl_xor_sync(0xFFFFFFFFu, q0, d);
                q1 += __shfl_xor_sync(0xFFFFFFFFu, q1, d);
            }
            if (lid < 4) {
                int prow = (int)blockIdx.y * 2 + (wid & 1);
                int col  = bn + wn + j * 8 + (lid & 3) * 2;
                *(float2*)&ps2[(size_t)prow * HD + col] = make_float2(s0, s1);
                *(float2*)&pq2[(size_t)prow * HD + col] = make_float2(q0, q1);
            }
        }
    } else {
        float* trans = (float*)smraw;
        __syncthreads();
#pragma unroll
        for (int j = 0; j < 4; j++) {
            int n0 = wn + j * 8 + col0;
            float s0 = scale[bn + n0], s1 = scale[bn + n0 + 1];
#pragma unroll
            for (int i = 0; i < 4; i++) {
                int t0 = wm + i * 16 + row0;
                __half2 v0 = *(__half2*)&acc[i][j][0];
                __half2 v1 = *(__half2*)&acc[i][j][1];
                trans[n0 * 132 + t0]           = __low2float(v0) * s0;
                trans[(n0 + 1) * 132 + t0]     = __high2float(v0) * s1;
                trans[n0 * 132 + t0 + 8]       = __low2float(v1) * s0;
                trans[(n0 + 1) * 132 + t0 + 8] = __high2float(v1) * s1;
            }
        }
        __syncthreads();
        float* y = (float*)Cv;
        const int b0 = bm >> 9;
        const int tb = bm & 511;
        const int n = tid >> 1, half = tid & 1;
        float* yp = y + ((size_t)b0 * FIN + bn + n) * TD + tb + half * 64;
        const float* sp = trans + n * 132 + half * 64;
#pragma unroll
        for (int k = 0; k < 16; k++)
            *(float4*)&yp[k * 4] = *(const float4*)&sp[k * 4];
    }
}

// ---------------- prep kernels -------------------------------------------------
__global__ void transpose_split2(const float* __restrict__ x, __half* __restrict__ xt2) {
    __shared__ float tile[32][33];
    int n = blockIdx.z, t0 = blockIdx.x * 32, f0 = blockIdx.y * 32;
    const float* xp = x + (size_t)n * FIN * TD;
#pragma unroll
    for (int i = 0; i < 4; i++) {
        int f = f0 + threadIdx.y + i * 8;
        tile[threadIdx.y + i * 8][threadIdx.x] = xp[(size_t)f * TD + t0 + threadIdx.x];
    }
    __syncthreads();
#pragma unroll
    for (int i = 0; i < 4; i++) {
        int t = t0 + threadIdx.y + i * 8;
        int f = f0 + threadIdx.x;
        float v = tile[threadIdx.x][threadIdx.y + i * 8];
        __half hi = __float2half_rn(v);
        float r1 = v - __half2float(hi);
        __half lo = __float2half_rn(r1);
        size_t row = (size_t)((size_t)n * TD + t) * 1024;
        xt2[row + f] = hi;
        xt2[row + 512 + f] = lo;
    }
}

// all weight binarization in ONE launch: W1 (2x replicated) + W2 + W3 + W4
__global__ void binw_fused(const float* __restrict__ W1, const float* __restrict__ W2,
                           const float* __restrict__ W3, const float* __restrict__ W4,
                           __half* __restrict__ w1b, __half* __restrict__ wb) {
    const int C1 = HD * FIN / 8;
    const int C2 = C1 + HD * HD / 8;
    const int C3 = C2 + HD * HD / 8;
    const int C4 = C3 + FIN * HD / 8;
    int i = blockIdx.x * 256 + threadIdx.x;
    if (i >= C4) return;
    const float* src;
    size_t off;
    __half* dst;
    size_t dof;
    bool rep = false;
    if (i < C1) {
        src = W1; off = (size_t)i * 8;
        int row = (i * 8) >> 9, k = (i * 8) & 511;
        dst = w1b; dof = (size_t)row * 1024 + k; rep = true;
    } else if (i < C2) {
        src = W2; off = (size_t)(i - C1) * 8; dst = wb; dof = (size_t)(i - C1) * 8;
    } else if (i < C3) {
        src = W3; off = (size_t)(i - C2) * 8;
        dst = wb; dof = (size_t)HD * HD + (size_t)(i - C2) * 8;
    } else {
        src = W4; off = (size_t)(i - C3) * 8;
        dst = wb; dof = (size_t)2 * HD * HD + (size_t)(i - C3) * 8;
    }
    float4 w0 = *(const float4*)&src[off];
    float4 w1 = *(const float4*)&src[off + 4];
    __half2 p0 = __floats2half2_rn(sgnf(w0.x), sgnf(w0.y));
    __half2 p1 = __floats2half2_rn(sgnf(w0.z), sgnf(w0.w));
    __half2 p2 = __floats2half2_rn(sgnf(w1.x), sgnf(w1.y));
    __half2 p3 = __floats2half2_rn(sgnf(w1.z), sgnf(w1.w));
    uint4 v;
    v.x = *(uint32_t*)&p0; v.y = *(uint32_t*)&p1;
    v.z = *(uint32_t*)&p2; v.w = *(uint32_t*)&p3;
    *(uint4*)&dst[dof] = v;
    if (rep) *(uint4*)&dst[dof + 512] = v;
}

// ---------------- BN stats: parallel 128-partial reduce --------------------------
__global__ void stats_final128(const float* __restrict__ ps2, const float* __restrict__ pq2,
                               float* __restrict__ mu, float* __restrict__ rs) {
    const int c = threadIdx.x & 31, lane = threadIdx.x >> 5;
    const int col = blockIdx.x * 32 + c;
    const int p0 = lane * 16;
    float s = 0.f, sq = 0.f;
#pragma unroll
    for (int p = 0; p < 16; p++) {
        s  += ps2[(size_t)(p0 + p) * HD + col];
        sq += pq2[(size_t)(p0 + p) * HD + col];
    }
    __shared__ float ss[8][33], sv[8][33];
    ss[lane][c] = s; sv[lane][c] = sq;
    __syncthreads();
    if (lane == 0) {
        float ts = 0.f, tq = 0.f;
#pragma unroll
        for (int l = 0; l < 8; l++) { ts += ss[l][c]; tq += sv[l][c]; }
        float m = ts * (1.f / MR);
        float var = tq * (1.f / MR) - m * m;
        if (var < 0.f) var = 0.f;
        mu[col] = m;
        rs[col] = rsqrtf(var + 1e-5f);
    }
}

// ---------------- sign activations: dual-row (shared column gathers) -------------
__global__ void sign_act_f32(const float* __restrict__ h,
                             const float* __restrict__ mu, const float* __restrict__ rs,
                             const float* __restrict__ g, const float* __restrict__ b,
                             __half* __restrict__ a) {
    size_t i8 = (size_t)blockIdx.x * blockDim.x + threadIdx.x;
    size_t e0 = i8 * 8;
    const size_t HALF = (size_t)(MR / 2) * HD;
    if (e0 >= HALF) return;
    int j = (int)(e0 % HD);
    float4 m0 = *(const float4*)&mu[j], m1 = *(const float4*)&mu[j + 4];
    float4 r0 = *(const float4*)&rs[j], r1 = *(const float4*)&rs[j + 4];
    float4 g0 = *(const float4*)&g[j],  g1 = *(const float4*)&g[j + 4];
    float4 b0 = *(const float4*)&b[j],  b1 = *(const float4*)&b[j + 4];
#pragma unroll
    for (int half = 0; half < 2; half++) {
        size_t e = e0 + (size_t)half * HALF;
        float4 h0 = *(const float4*)&h[e];
        float4 h1 = *(const float4*)&h[e + 4];
        __half2 p0 = __floats2half2_rn(sgnf(g0.x * (h0.x - m0.x) * r0.x + b0.x),
                                       sgnf(g0.y * (h0.y - m0.y) * r0.y + b0.y));
        __half2 p1 = __floats2half2_rn(sgnf(g0.z * (h0.z - m0.z) * r0.z + b0.z),
                                       sgnf(g0.w * (h0.w - m0.w) * r0.w + b0.w));
        __half2 p2 = __floats2half2_rn(sgnf(g1.x * (h1.x - m1.x) * r1.x + b1.x),
                                       sgnf(g1.y * (h1.y - m1.y) * r1.y + b1.y));
        __half2 p3 = __floats2half2_rn(sgnf(g1.z * (h1.z - m1.z) * r1.z + b1.z),
                                       sgnf(g1.w * (h1.w - m1.w) * r1.w + b1.w));
        uint4 v;
        v.x = *(uint32_t*)&p0; v.y = *(uint32_t*)&p1;
        v.z = *(uint32_t*)&p2; v.w = *(uint32_t*)&p3;
        *(uint4*)&a[e] = v;
    }
}
__global__ void sign_act_f16(const __half* __restrict__ h,
                             const float* __restrict__ mu, const float* __restrict__ rs,
                             const float* __restrict__ g, const float* __restrict__ b,
                             __half* __restrict__ a) {
    size_t i8 = (size_t)blockIdx.x * blockDim.x + threadIdx.x;
    size_t e0 = i8 * 8;
    const size_t HALF = (size_t)(MR / 2) * HD;
    if (e0 >= HALF) return;
    int j = (int)(e0 % HD);
    float4 m0 = *(const float4*)&mu[j], m1 = *(const float4*)&mu[j + 4];
    float4 r0 = *(const float4*)&rs[j], r1 = *(const float4*)&rs[j + 4];
    float4 g0 = *(const float4*)&g[j],  g1 = *(const float4*)&g[j + 4];
    float4 b0 = *(const float4*)&b[j],  b1 = *(const float4*)&b[j + 4];
#pragma unroll
    for (int half = 0; half < 2; half++) {
        size_t e = e0 + (size_t)half * HALF;
        uint4 hv = *(const uint4*)&h[e];
        const __half2* hp = (const __half2*)&hv;
        __half2 p0 = __floats2half2_rn(
            sgnf(g0.x * (__low2float(hp[0]) - m0.x) * r0.x + b0.x),
            sgnf(g0.y * (__high2float(hp[0]) - m0.y) * r0.y + b0.y));
        __half2 p1 = __floats2half2_rn(
            sgnf(g0.z * (__low2float(hp[1]) - m0.z) * r0.z + b0.z),
            sgnf(g0.w * (__high2float(hp[1]) - m0.w) * r0.w + b0.w));
        __half2 p2 = __floats2half2_rn(
            sgnf(g1.x * (__low2float(hp[2]) - m1.x) * r1.x + b1.x),
            sgnf(g1.y * (__high2float(hp[2]) - m1.y) * r1.y + b1.y));
        __half2 p3 = __floats2half2_rn(
            sgnf(g1.z * (__low2float(hp[3]) - m1.z) * r1.z + b1.z),
            sgnf(g1.w * (__high2float(hp[3]) - m1.w) * r1.w + b1.w));
        uint4 v;
        v.x = *(uint32_t*)&p0; v.y = *(uint32_t*)&p1;
        v.z = *(uint32_t*)&p2; v.w = *(uint32_t*)&p3;
        *(uint4*)&a[e] = v;
    }
}

// ---------------- host orchestration --------------------------------------------
extern "C" void kernel_launch(void* const* d_in, const int* in_sizes, int n_in,
                              void* d_out, int out_size) {
    const float* x     = (const float*)d_in[0];
    const float* W1    = (const float*)d_in[2];
    const float* g1    = (const float*)d_in[3];
    const float* b1    = (const float*)d_in[4];
    const float* W2    = (const float*)d_in[5];
    const float* g2    = (const float*)d_in[6];
    const float* b2    = (const float*)d_in[7];
    const float* W3    = (const float*)d_in[8];
    const float* g3    = (const float*)d_in[9];
    const float* b3    = (const float*)d_in[10];
    const float* W4    = (const float*)d_in[11];
    const float* scale = (const float*)d_in[12];
    float* y = (float*)d_out;

    __half *xt2, *w1b, *wb, *a;
    float *h, *mu, *rs, *ps2, *pq2;
    cudaGetSymbolAddress((void**)&xt2, g_xt2);
    cudaGetSymbolAddress((void**)&w1b, g_w1b);
    cudaGetSymbolAddress((void**)&wb,  g_wb);
    cudaGetSymbolAddress((void**)&h,   g_h);
    cudaGetSymbolAddress((void**)&a,   g_a);
    cudaGetSymbolAddress((void**)&mu,  g_mu);
    cudaGetSymbolAddress((void**)&rs,  g_rs);
    cudaGetSymbolAddress((void**)&ps2, g_ps2);
    cudaGetSymbolAddress((void**)&pq2, g_pq2);
    __half* h16 = (__half*)h;
    __half* w2b = wb;
    __half* w3b = wb + (size_t)HD * HD;
    __half* w4b = wb + (size_t)2 * HD * HD;

    cudaFuncSetAttribute(gemm_l1,     cudaFuncAttributeMaxDynamicSharedMemorySize, SMEM_L1);
    cudaFuncSetAttribute(gemm_f16<0>, cudaFuncAttributeMaxDynamicSharedMemorySize, SMEM_F16);
    cudaFuncSetAttribute(gemm_f16<1>, cudaFuncAttributeMaxDynamicSharedMemorySize, SMEM_F16);

    // prep
    transpose_split2<<<dim3(TD / 32, FIN / 32, NB), dim3(32, 8)>>>(x, xt2);
    {
        int chunks = (HD * FIN + 2 * HD * HD + FIN * HD) / 8;
        binw_fused<<<(chunks + 255) / 256, 256>>>(W1, W2, W3, W4, w1b, wb);
    }

    dim3 blk(256);
    dim3 gridSign((unsigned)(((size_t)MR * HD / 16 + 255) / 256));
    dim3 gridStats(HD / 32);
    dim3 gGemm(HD / BN, MR / BM);   // (16, 64)
    dim3 gGemm4(FIN / BN, MR / BM); // (4, 64)

    // layer 1 (f16 2-way split, f32 accum, K=1024, fused stats)
    gemm_l1<<<gGemm, blk, SMEM_L1>>>(xt2, w1b, h, HD, 1024, ps2, pq2);
    stats_final128<<<gridStats, blk>>>(ps2, pq2, mu, rs);
    sign_act_f32<<<gridSign, blk>>>(h, mu, rs, g1, b1, a);

    // layer 2
    gemm_f16<0><<<gGemm, blk, SMEM_F16>>>(a, w2b, h16, HD, HD, nullptr, ps2, pq2);
    stats_final128<<<gridStats, blk>>>(ps2, pq2, mu, rs);
    sign_act_f16<<<gridSign, blk>>>(h16, mu, rs, g2, b2, a);

    // layer 3
    gemm_f16<0><<<gGemm, blk, SMEM_F16>>>(a, w3b, h16, HD, HD, nullptr, ps2, pq2);
    stats_final128<<<gridStats, blk>>>(ps2, pq2, mu, rs);
    sign_act_f16<<<gridSign, blk>>>(h16, mu, rs, g3, b3, a);

    // layer 4
    gemm_f16<1><<<gGemm4, blk, SMEM_F16>>>(a, w4b, y, FIN, HD, scale, nullptr, nullptr);
}